// round 1
// baseline (speedup 1.0000x reference)
#include <cuda_runtime.h>
#include <cuda_fp16.h>

// FourierKAN: y[b,j] = sum_{i,g} cos((g+1)x[b,i]) C0[j,i,g] + sin((g+1)x[b,i]) C1[j,i,g] + bias[j]
// Strategy: prep kernel transposes coeffs -> fp16 Wt[j][k] (k = i*64 + trig*32 + g),
// fused kernel generates trig features via angle-addition recurrence into smem and
// runs an mma.sync.m16n8k16 fp16 GEMM with fp32 accumulation.

#define IN_DIM   256
#define OUT_DIM  256
#define GRID_SZ  32
#define KTOT     (IN_DIM * 64)   // 16384 = in * (2 trig * 32 grid)

#define BM  128
#define BN  64
#define KC  64                   // k-slice per step: one input dim (32 cos + 32 sin)
#define PAD 8
#define LDA (KC + PAD)           // 72 halfs -> 144B row stride (16B aligned, conflict-free frags)
#define LDB (KC + PAD)

// fp16 transposed coefficients, [OUT_DIM][KTOT]; 8.4 MB static scratch (fits in L2).
__device__ __half g_Wt[OUT_DIM * KTOT];

// ---------------------------------------------------------------------------
// Kernel A: coeffs fp32 [2][out][in][grid] -> fp16 Wt[j][i*64 + t*32 + g]
// One thread per float4 group (4 g values). Total groups = 2*256*256*8 = 2^20.
// ---------------------------------------------------------------------------
__global__ void __launch_bounds__(256) prep_coeffs_kernel(const float* __restrict__ C) {
    int idx = blockIdx.x * blockDim.x + threadIdx.x;   // 0 .. 2^20-1
    int g4 = idx & 7;
    int i  = (idx >> 3) & 255;
    int j  = (idx >> 11) & 255;
    int t  = idx >> 19;                                 // 0 or 1
    float4 v = reinterpret_cast<const float4*>(C)[idx];
    __half2 h0 = __floats2half2_rn(v.x, v.y);
    __half2 h1 = __floats2half2_rn(v.z, v.w);
    uint2 o;
    o.x = *reinterpret_cast<unsigned*>(&h0);
    o.y = *reinterpret_cast<unsigned*>(&h1);
    int k = i * 64 + t * 32 + g4 * 4;
    *reinterpret_cast<uint2*>(&g_Wt[j * KTOT + k]) = o;
}

// ---------------------------------------------------------------------------
// mma.sync m16n8k16 row.col f32.f16.f16.f32
// ---------------------------------------------------------------------------
__device__ __forceinline__ void mma16816(float c[4], const unsigned a[4], const unsigned b[2]) {
    asm volatile(
        "mma.sync.aligned.m16n8k16.row.col.f32.f16.f16.f32 "
        "{%0,%1,%2,%3}, {%4,%5,%6,%7}, {%8,%9}, {%0,%1,%2,%3};\n"
        : "+f"(c[0]), "+f"(c[1]), "+f"(c[2]), "+f"(c[3])
        : "r"(a[0]), "r"(a[1]), "r"(a[2]), "r"(a[3]), "r"(b[0]), "r"(b[1]));
}

// ---------------------------------------------------------------------------
// Fused main kernel: CTA computes out tile [BM x BN].
// Per i-step: generate feature slice As[BM][64] (cos|sin via recurrence),
// load Wt slice Bs[BN][64] (L2-resident), run 4 k16 mma steps per warp.
// 8 warps: warp_m = wid%4 (32 rows), warp_n = wid/4 (32 cols):
//   per warp 2 m-frags x 4 n-frags of m16n8.
// ---------------------------------------------------------------------------
__global__ void __launch_bounds__(256) fkan_main_kernel(
    const float* __restrict__ x,
    const float* __restrict__ bias,
    float* __restrict__ out)
{
    __shared__ __half As[BM][LDA];
    __shared__ __half Bs[BN][LDB];

    const int tid  = threadIdx.x;
    const int lane = tid & 31;
    const int wid  = tid >> 5;
    const int m0   = blockIdx.y * BM;
    const int n0   = blockIdx.x * BN;

    const int warp_m = (wid & 3) * 32;
    const int warp_n = (wid >> 2) * 32;

    float acc[2][4][4];
#pragma unroll
    for (int a = 0; a < 2; ++a)
#pragma unroll
        for (int b = 0; b < 4; ++b)
#pragma unroll
            for (int c = 0; c < 4; ++c) acc[a][b][c] = 0.0f;

    // feature generation role: 2 threads per row; fhalf 0 -> cos cols [0,32), 1 -> sin cols [32,64)
    const int frow  = tid & 127;
    const int fhalf = tid >> 7;
    const float* xrow = x + (size_t)(m0 + frow) * IN_DIM;

    // B-load role: 8 threads per j-row (128B), 32 rows per pass, 2 passes
    const int bj  = tid >> 3;       // 0..31
    const int seg = tid & 7;        // 0..7 (16B segments)

    for (int i = 0; i < IN_DIM; ++i) {
        // ---- load B tile (global fp16, L2-resident) ----
        {
            const __half* srcbase = &g_Wt[(size_t)(n0 + bj) * KTOT + i * 64 + seg * 8];
            uint4 v0 = *reinterpret_cast<const uint4*>(srcbase);
            uint4 v1 = *reinterpret_cast<const uint4*>(srcbase + (size_t)32 * KTOT);
            *reinterpret_cast<uint4*>(&Bs[bj][seg * 8])      = v0;
            *reinterpret_cast<uint4*>(&Bs[bj + 32][seg * 8]) = v1;
        }

        // ---- generate trig features via recurrence ----
        {
            float xv = xrow[i];
            float s1, c1;
            sincosf(xv, &s1, &c1);
            float ck = c1, sk = s1;   // g=0 -> cos(x), sin(x)  (k=1 in reference)
            __half2 buf[16];
#pragma unroll
            for (int g2 = 0; g2 < 16; ++g2) {
                float v0 = fhalf ? sk : ck;
                float nc = ck * c1 - sk * s1;
                float ns = sk * c1 + ck * s1;
                ck = nc; sk = ns;
                float v1 = fhalf ? sk : ck;
                nc = ck * c1 - sk * s1;
                ns = sk * c1 + ck * s1;
                ck = nc; sk = ns;
                buf[g2] = __floats2half2_rn(v0, v1);
            }
            uint4* dst = reinterpret_cast<uint4*>(&As[frow][fhalf * 32]);
            const uint4* srcb = reinterpret_cast<const uint4*>(buf);
#pragma unroll
            for (int q = 0; q < 4; ++q) dst[q] = srcb[q];
        }

        __syncthreads();

        // ---- mma over 4 k16 steps ----
#pragma unroll
        for (int kk = 0; kk < 4; ++kk) {
            const int k0 = kk * 16;
            unsigned afrag[2][4];
#pragma unroll
            for (int mf = 0; mf < 2; ++mf) {
                const __half* ab = &As[warp_m + mf * 16 + (lane >> 2)][k0 + ((lane & 3) << 1)];
                afrag[mf][0] = *reinterpret_cast<const unsigned*>(ab);
                afrag[mf][1] = *reinterpret_cast<const unsigned*>(ab + 8 * LDA);
                afrag[mf][2] = *reinterpret_cast<const unsigned*>(ab + 8);
                afrag[mf][3] = *reinterpret_cast<const unsigned*>(ab + 8 * LDA + 8);
            }
            unsigned bfrag[4][2];
#pragma unroll
            for (int nf = 0; nf < 4; ++nf) {
                const __half* bb = &Bs[warp_n + nf * 8 + (lane >> 2)][k0 + ((lane & 3) << 1)];
                bfrag[nf][0] = *reinterpret_cast<const unsigned*>(bb);
                bfrag[nf][1] = *reinterpret_cast<const unsigned*>(bb + 8);
            }
#pragma unroll
            for (int mf = 0; mf < 2; ++mf)
#pragma unroll
                for (int nf = 0; nf < 4; ++nf)
                    mma16816(acc[mf][nf], afrag[mf], bfrag[nf]);
        }

        __syncthreads();
    }

    // ---- epilogue: add bias, write fp32 ----
#pragma unroll
    for (int mf = 0; mf < 2; ++mf) {
#pragma unroll
        for (int nf = 0; nf < 4; ++nf) {
            int r = m0 + warp_m + mf * 16 + (lane >> 2);
            int c = n0 + warp_n + nf * 8 + ((lane & 3) << 1);
            float b0 = bias[c];
            float b1 = bias[c + 1];
            out[(size_t)r * OUT_DIM + c]           = acc[mf][nf][0] + b0;
            out[(size_t)r * OUT_DIM + c + 1]       = acc[mf][nf][1] + b1;
            out[(size_t)(r + 8) * OUT_DIM + c]     = acc[mf][nf][2] + b0;
            out[(size_t)(r + 8) * OUT_DIM + c + 1] = acc[mf][nf][3] + b1;
        }
    }
}

extern "C" void kernel_launch(void* const* d_in, const int* in_sizes, int n_in,
                              void* d_out, int out_size) {
    const float* x      = (const float*)d_in[0];   // [Mrows, 256]
    const float* coeffs = (const float*)d_in[1];   // [2, 256, 256, 32]
    const float* bias   = (const float*)d_in[2];   // [1, 256]
    float* out = (float*)d_out;

    int Mrows = in_sizes[0] / IN_DIM;              // 4096

    // Kernel A: transpose + fp16 convert coefficients into g_Wt
    prep_coeffs_kernel<<<(2 * OUT_DIM * IN_DIM * GRID_SZ / 4) / 256, 256>>>(coeffs);

    // Fused feature-gen + GEMM
    dim3 grid(OUT_DIM / BN, Mrows / BM);           // (4, 32) = 128 CTAs
    fkan_main_kernel<<<grid, 256>>>(x, bias, out);
}

// round 2
// speedup vs baseline: 1.3644x; 1.3644x over previous
#include <cuda_runtime.h>
#include <cuda_fp16.h>

// FourierKAN fused feature-gen + fp16 tensor-core GEMM, pipelined.
// y[b,j] = sum_{i,g} cos((g+1)x[b,i]) C0[j,i,g] + sin((g+1)x[b,i]) C1[j,i,g] + bias[j]
// k-index layout (permuted for vectorized feature writes):
//   k = i*64 + trig*32 + (g&1)*16 + (g>>1)     (g 0-based, multiplier g+1)

#define IN_DIM   256
#define OUT_DIM  256
#define GRID_SZ  32
#define KTOT     (IN_DIM * 64)

#define BM  64
#define BN  64
#define KC  64
#define PAD 8
#define LDR (KC + PAD)           // 72 halfs = 144B row stride; 16B-aligned, LDSM conflict-free

__device__ __half g_Wt[OUT_DIM * KTOT];   // 8.4 MB, L2-resident

__device__ __forceinline__ unsigned sptr(const void* p) {
    return (unsigned)__cvta_generic_to_shared(p);
}

#define CP_ASYNC16(dst, src) \
    asm volatile("cp.async.cg.shared.global [%0], [%1], 16;\n" :: "r"(dst), "l"(src))
#define CP_COMMIT() asm volatile("cp.async.commit_group;\n" ::)
#define CP_WAIT0()  asm volatile("cp.async.wait_group 0;\n" ::)

// ---------------------------------------------------------------------------
// Prep: coeffs fp32 [2][out][in][grid] -> fp16 g_Wt[j][k], k per layout above.
// One thread per float4 (4 consecutive g = 4a..4a+3).
// ---------------------------------------------------------------------------
__global__ void __launch_bounds__(256) prep_coeffs_kernel(const float* __restrict__ C) {
    int idx = blockIdx.x * blockDim.x + threadIdx.x;   // 0 .. 2^20-1
    int a  = idx & 7;            // g-quad index: g = 4a..4a+3
    int i  = (idx >> 3) & 255;
    int j  = (idx >> 11) & 255;
    int t  = idx >> 19;          // trig: 0 cos, 1 sin
    float4 v = reinterpret_cast<const float4*>(C)[idx];
    // g=4a   -> par0, pos 2a      (v.x)
    // g=4a+1 -> par1, pos 2a      (v.y)
    // g=4a+2 -> par0, pos 2a+1    (v.z)
    // g=4a+3 -> par1, pos 2a+1    (v.w)
    __half2 p0 = __floats2half2_rn(v.x, v.z);
    __half2 p1 = __floats2half2_rn(v.y, v.w);
    __half* base = &g_Wt[(size_t)j * KTOT + i * 64 + t * 32];
    *reinterpret_cast<__half2*>(base + 2 * a)      = p0;
    *reinterpret_cast<__half2*>(base + 16 + 2 * a) = p1;
}

// ---------------------------------------------------------------------------
// mma.sync m16n8k16 row.col f32.f16.f16.f32
// ---------------------------------------------------------------------------
__device__ __forceinline__ void mma16816(float c[4], const unsigned a[4], const unsigned* b) {
    asm volatile(
        "mma.sync.aligned.m16n8k16.row.col.f32.f16.f16.f32 "
        "{%0,%1,%2,%3}, {%4,%5,%6,%7}, {%8,%9}, {%0,%1,%2,%3};\n"
        : "+f"(c[0]), "+f"(c[1]), "+f"(c[2]), "+f"(c[3])
        : "r"(a[0]), "r"(a[1]), "r"(a[2]), "r"(a[3]), "r"(b[0]), "r"(b[1]));
}

__device__ __forceinline__ void ldsm_x4(unsigned r[4], unsigned addr) {
    asm volatile("ldmatrix.sync.aligned.m8n8.x4.shared.b16 {%0,%1,%2,%3}, [%4];\n"
                 : "=r"(r[0]), "=r"(r[1]), "=r"(r[2]), "=r"(r[3]) : "r"(addr));
}

// ---------------------------------------------------------------------------
// Main fused kernel. CTA tile [64 x 64], 256 threads (8 warps), 2 CTAs/SM.
// Double-buffered As/Bs, cp.async B, one __syncthreads per i-step.
// Warps: warp_m = (wid&1)*32 (2 m16 frags), warp_n = (wid>>1)*16 (2 n8 frags).
// ---------------------------------------------------------------------------
__global__ void __launch_bounds__(256, 2) fkan_main_kernel(
    const float* __restrict__ x,
    const float* __restrict__ bias,
    float* __restrict__ out)
{
    __shared__ __half As[2][BM][LDR];
    __shared__ __half Bs[2][BN][LDR];

    const int tid  = threadIdx.x;
    const int lane = tid & 31;
    const int wid  = tid >> 5;
    const int m0   = blockIdx.y * BM;
    const int n0   = blockIdx.x * BN;

    const int warp_m = (wid & 1) * 32;
    const int warp_n = (wid >> 1) * 16;

    float acc[2][2][4];
#pragma unroll
    for (int a = 0; a < 2; ++a)
#pragma unroll
        for (int b = 0; b < 2; ++b)
#pragma unroll
            for (int c = 0; c < 4; ++c) acc[a][b][c] = 0.0f;

    // ---- role constants ----
    // feature gen: 4 threads/row: fhalf selects cos/sin, fpar selects g parity
    const int frow  = tid >> 2;
    const int fsub  = tid & 3;
    const int fhalf = fsub >> 1;
    const int fpar  = fsub & 1;
    const float* xrow = x + (size_t)(m0 + frow) * IN_DIM;

    // B cp.async: 8 threads per 128B row, 32 rows/pass, 2 passes
    const int bj  = tid >> 3;
    const int seg = tid & 7;
    const __half* bsrc = &g_Wt[(size_t)(n0 + bj) * KTOT + seg * 8];

    // smem bases
    const unsigned asBase[2] = { sptr(&As[0][0][0]), sptr(&As[1][0][0]) };
    const unsigned bsBase[2] = { sptr(&Bs[0][0][0]), sptr(&Bs[1][0][0]) };

    // ldmatrix per-thread offsets
    const int sel = lane >> 3;          // which 8x8 matrix this lane addresses
    const int rr  = lane & 7;
    // A x4 for m-frag mf: mats (m0-7,k0)(m8-15,k0)(m0-7,k8)(m8-15,k8)
    unsigned aOff[2];
#pragma unroll
    for (int mf = 0; mf < 2; ++mf)
        aOff[mf] = (unsigned)((warp_m + mf * 16 + (sel & 1) * 8 + rr) * (LDR * 2)
                              + (sel >> 1) * 16);
    // B x4: mats (n0-7,k0)(n0-7,k8)(n8-15,k0)(n8-15,k8)
    const unsigned bOff = (unsigned)((warp_n + (sel >> 1) * 8 + rr) * (LDR * 2)
                                     + (sel & 1) * 16);

    // feature STS destination offset within a buffer
    const unsigned fDst = (unsigned)(frow * (LDR * 2) + (fhalf * 32 + fpar * 16) * 2);

    // ---- helpers ----
    auto loadB = [&](int buf, int i) {
        unsigned d = bsBase[buf] + (unsigned)(bj * (LDR * 2) + seg * 16);
        const __half* s = bsrc + i * 64;
        CP_ASYNC16(d, s);
        CP_ASYNC16(d + 32u * (LDR * 2), s + (size_t)32 * KTOT);
    };

    auto genA = [&](int buf, int i) {
        float xv = __ldg(&xrow[i]);
        float s1, c1;
        sincosf(xv, &s1, &c1);
        float c2 = __fmaf_rn(2.f * c1, c1, -1.f);   // cos 2x
        float s2 = 2.f * s1 * c1;                   // sin 2x
        float ck = fpar ? c2 : c1;
        float sk = fpar ? s2 : s1;
        __half2 fb[8];
#pragma unroll
        for (int t = 0; t < 8; ++t) {
            float v0 = fhalf ? sk : ck;
            float nc = ck * c2 - sk * s2;
            float ns = sk * c2 + ck * s2;
            ck = nc; sk = ns;
            float v1 = fhalf ? sk : ck;
            nc = ck * c2 - sk * s2;
            ns = sk * c2 + ck * s2;
            ck = nc; sk = ns;
            fb[t] = __floats2half2_rn(v0, v1);
        }
        uint4* dst = reinterpret_cast<uint4*>(
            reinterpret_cast<char*>(&As[buf][0][0]) + fDst);
        const uint4* srcb = reinterpret_cast<const uint4*>(fb);
        dst[0] = srcb[0];
        dst[1] = srcb[1];
    };

    // ---- prologue ----
    loadB(0, 0);
    CP_COMMIT();
    genA(0, 0);
    CP_WAIT0();
    __syncthreads();

    // ---- main loop ----
    for (int i = 0; i < IN_DIM; ++i) {
        const int cur = i & 1;
        const int nxt = cur ^ 1;

        if (i + 1 < IN_DIM) {
            loadB(nxt, i + 1);
            CP_COMMIT();
        }

        // load all fragments for this i-step
        unsigned afr[2][4][4];   // [mf][kk][reg]
        unsigned bfr[4][4];      // [kk][reg]  (nf0 = regs 0,1; nf1 = regs 2,3)
#pragma unroll
        for (int kk = 0; kk < 4; ++kk) {
            unsigned kByte = (unsigned)(kk * 32);
#pragma unroll
            for (int mf = 0; mf < 2; ++mf)
                ldsm_x4(afr[mf][kk], asBase[cur] + aOff[mf] + kByte);
            ldsm_x4(bfr[kk], bsBase[cur] + bOff + kByte);
        }

        // generate next i-step features (independent chain, overlaps mma issue)
        if (i + 1 < IN_DIM) genA(nxt, i + 1);

        // mma
#pragma unroll
        for (int kk = 0; kk < 4; ++kk) {
#pragma unroll
            for (int mf = 0; mf < 2; ++mf) {
                mma16816(acc[mf][0], afr[mf][kk], &bfr[kk][0]);
                mma16816(acc[mf][1], afr[mf][kk], &bfr[kk][2]);
            }
        }

        CP_WAIT0();
        __syncthreads();
    }

    // ---- epilogue: bias + fp32 store ----
#pragma unroll
    for (int mf = 0; mf < 2; ++mf) {
#pragma unroll
        for (int nf = 0; nf < 2; ++nf) {
            int r = m0 + warp_m + mf * 16 + (lane >> 2);
            int c = n0 + warp_n + nf * 8 + ((lane & 3) << 1);
            float b0 = bias[c];
            float b1 = bias[c + 1];
            out[(size_t)r * OUT_DIM + c]           = acc[mf][nf][0] + b0;
            out[(size_t)r * OUT_DIM + c + 1]       = acc[mf][nf][1] + b1;
            out[(size_t)(r + 8) * OUT_DIM + c]     = acc[mf][nf][2] + b0;
            out[(size_t)(r + 8) * OUT_DIM + c + 1] = acc[mf][nf][3] + b1;
        }
    }
}

extern "C" void kernel_launch(void* const* d_in, const int* in_sizes, int n_in,
                              void* d_out, int out_size) {
    const float* x      = (const float*)d_in[0];   // [M, 256]
    const float* coeffs = (const float*)d_in[1];   // [2, 256, 256, 32]
    const float* bias   = (const float*)d_in[2];   // [1, 256]
    float* out = (float*)d_out;

    int Mrows = in_sizes[0] / IN_DIM;              // 4096

    prep_coeffs_kernel<<<(2 * OUT_DIM * IN_DIM * GRID_SZ / 4) / 256, 256>>>(coeffs);

    dim3 grid(OUT_DIM / BN, Mrows / BM);           // (4, 64) = 256 CTAs
    fkan_main_kernel<<<grid, 256>>>(x, bias, out);
}

// round 4
// speedup vs baseline: 1.6279x; 1.1931x over previous
#include <cuda_runtime.h>
#include <cuda_fp16.h>
#include <cstdint>

// FourierKAN fused feature-gen + mma.sync fp16 GEMM (compute_103-safe).
// y[b,j] = sum_{i,g} cos((g+1)x_bi)C0[j,i,g] + sin((g+1)x_bi)C1[j,i,g] + bias[j]
// k layout: k = i*64 + 2*g + trig  (g 0-based; even k = cos, odd k = sin)
// CTA tile 128x256 (full N), 8 warps (2m x 4n), warp tile 64x64, split-K x4.

#define IN_DIM   256
#define OUT_DIM  256
#define KTOT     (IN_DIM * 64)
#define BM       128
#define BN       256
#define ISPLIT   4
#define IPER     (IN_DIM / ISPLIT)   // 64
#define M_MAX    4096

#define LDRB     144                 // row stride bytes (72 halfs): pad -> conflict-free

// dynamic smem offsets
#define OFF_A0   0
#define OFF_A1   18432               // 128*144
#define OFF_B0   36864
#define OFF_B1   73728               // + 256*144
#define SMEM_BYTES 110592

__device__ __half g_Wt[OUT_DIM * KTOT];              // 8.4 MB (L2-resident)
__device__ float  g_part[ISPLIT * M_MAX * OUT_DIM];  // 16 MB split-K partials

__device__ __forceinline__ unsigned sptr(const void* p) {
    return (unsigned)__cvta_generic_to_shared(p);
}

#define CP_ASYNC16(dst, src) \
    asm volatile("cp.async.cg.shared.global [%0], [%1], 16;\n" :: "r"(dst), "l"(src))
#define CP_COMMIT() asm volatile("cp.async.commit_group;\n" ::)
#define CP_WAIT0()  asm volatile("cp.async.wait_group 0;\n" ::)

__device__ __forceinline__ void mma16816(float c[4], const unsigned a[4], const unsigned* b) {
    asm volatile(
        "mma.sync.aligned.m16n8k16.row.col.f32.f16.f16.f32 "
        "{%0,%1,%2,%3}, {%4,%5,%6,%7}, {%8,%9}, {%0,%1,%2,%3};\n"
        : "+f"(c[0]), "+f"(c[1]), "+f"(c[2]), "+f"(c[3])
        : "r"(a[0]), "r"(a[1]), "r"(a[2]), "r"(a[3]), "r"(b[0]), "r"(b[1]));
}
__device__ __forceinline__ void ldsm_x4(unsigned r[4], unsigned addr) {
    asm volatile("ldmatrix.sync.aligned.m8n8.x4.shared.b16 {%0,%1,%2,%3}, [%4];\n"
                 : "=r"(r[0]), "=r"(r[1]), "=r"(r[2]), "=r"(r[3]) : "r"(addr));
}

// ---------------------------------------------------------------------------
// Prep: coeffs fp32 [2][out][in][grid] -> fp16 g_Wt[j][i*64 + 2g + trig]
// Thread u handles (j,i, g-quad a): one uint4 (8 interleaved halves) store.
// ---------------------------------------------------------------------------
__global__ void __launch_bounds__(256) prep_coeffs_kernel(const float* __restrict__ C) {
    unsigned u = blockIdx.x * blockDim.x + threadIdx.x;   // 0 .. 2^19-1
    const float4* C4 = reinterpret_cast<const float4*>(C);
    float4 c = C4[u];                 // cos coeffs, g=4a..4a+3
    float4 s = C4[u + (1u << 19)];    // sin coeffs
    unsigned a = u & 7, i = (u >> 3) & 255, j = u >> 11;
    __half2 h0 = __floats2half2_rn(c.x, s.x);
    __half2 h1 = __floats2half2_rn(c.y, s.y);
    __half2 h2 = __floats2half2_rn(c.z, s.z);
    __half2 h3 = __floats2half2_rn(c.w, s.w);
    uint4 o;
    o.x = *reinterpret_cast<unsigned*>(&h0);
    o.y = *reinterpret_cast<unsigned*>(&h1);
    o.z = *reinterpret_cast<unsigned*>(&h2);
    o.w = *reinterpret_cast<unsigned*>(&h3);
    *reinterpret_cast<uint4*>(&g_Wt[(size_t)j * KTOT + i * 64 + a * 8]) = o;
}

// ---------------------------------------------------------------------------
// Main kernel: 256 threads, grid (ISPLIT, Mrows/BM).
// ---------------------------------------------------------------------------
__global__ void __launch_bounds__(256, 1) fkan_main_kernel(const float* __restrict__ x) {
    extern __shared__ char sm[];

    const int tid  = threadIdx.x;
    const int lane = tid & 31;
    const int wid  = tid >> 5;
    const int ks   = blockIdx.x;
    const int m0   = blockIdx.y * BM;
    const int i_begin = ks * IPER;

    const int warp_m = (wid & 1) * 64;
    const int warp_n = (wid >> 1) * 64;

    char* aPtr[2] = { sm + OFF_A0, sm + OFF_A1 };
    const unsigned aU32[2] = { sptr(sm + OFF_A0), sptr(sm + OFF_A1) };
    const unsigned bU32[2] = { sptr(sm + OFF_B0), sptr(sm + OFF_B1) };

    float acc[4][8][4];
#pragma unroll
    for (int a = 0; a < 4; ++a)
#pragma unroll
        for (int b = 0; b < 8; ++b)
#pragma unroll
            for (int c = 0; c < 4; ++c) acc[a][b][c] = 0.0f;

    // ---- roles ----
    const int grow = tid >> 1;          // feature row 0..127
    const int gh   = tid & 1;           // start parity (mult 1 or 2)
    const float* xsrc = x + (size_t)(m0 + grow) * IN_DIM + i_begin;

    const int bj = tid;                 // B row == output col 0..255
    const __half* bsrc = g_Wt + (size_t)bj * KTOT + i_begin * 64;

    // ldmatrix offsets (bytes within buffer)
    const int sel = lane >> 3;
    const int rr  = lane & 7;
    unsigned aOff[4];
#pragma unroll
    for (int mf = 0; mf < 4; ++mf)
        aOff[mf] = (unsigned)((warp_m + mf * 16 + (sel & 1) * 8 + rr) * LDRB
                              + (sel >> 1) * 16);
    unsigned bOff[4];
#pragma unroll
    for (int q = 0; q < 4; ++q)
        bOff[q] = (unsigned)((warp_n + q * 16 + (sel >> 1) * 8 + rr) * LDRB
                             + (sel & 1) * 16);

    auto loadB = [&](int buf, int ii) {
        const __half* s = bsrc + ii * 64;
        unsigned d = bU32[buf] + (unsigned)(bj * LDRB);
#pragma unroll
        for (int seg = 0; seg < 8; ++seg)
            CP_ASYNC16(d + seg * 16, s + seg * 8);
    };

    auto genA = [&](int buf, int ii) {
        float xv = __ldg(xsrc + ii);
        float s1, c1;
        sincosf(xv, &s1, &c1);
        float c2 = __fmaf_rn(2.f * c1, c1, -1.f);   // cos 2x
        float s2 = 2.f * s1 * c1;                   // sin 2x
        float ck = gh ? c2 : c1;                    // start mult = gh+1
        float sk = gh ? s2 : s1;
        __half* arow = reinterpret_cast<__half*>(aPtr[buf] + grow * LDRB) + 2 * gh;
#pragma unroll
        for (int n = 0; n < 16; ++n) {              // mult = gh+1 + 2n
            __half2 v = __floats2half2_rn(ck, sk);
            *reinterpret_cast<__half2*>(arow + 4 * n) = v;
            float nc = ck * c2 - sk * s2;
            float ns = sk * c2 + ck * s2;
            ck = nc; sk = ns;
        }
    };

    // ---- prologue ----
    loadB(0, 0);
    CP_COMMIT();
    genA(0, 0);
    CP_WAIT0();
    __syncthreads();

    // ---- main loop ----
    for (int ii = 0; ii < IPER; ++ii) {
        const int cur = ii & 1;
        const int nxt = cur ^ 1;

        if (ii + 1 < IPER) {
            loadB(nxt, ii + 1);
            CP_COMMIT();
            genA(nxt, ii + 1);
        }

#pragma unroll
        for (int kk = 0; kk < 4; ++kk) {
            const unsigned kB = (unsigned)(kk * 32);
            unsigned af[4][4], bf[4][4];
#pragma unroll
            for (int mf = 0; mf < 4; ++mf) ldsm_x4(af[mf], aU32[cur] + aOff[mf] + kB);
#pragma unroll
            for (int q = 0; q < 4; ++q)    ldsm_x4(bf[q],  bU32[cur] + bOff[q] + kB);
#pragma unroll
            for (int mf = 0; mf < 4; ++mf)
#pragma unroll
                for (int q = 0; q < 4; ++q) {
                    mma16816(acc[mf][2 * q],     af[mf], &bf[q][0]);
                    mma16816(acc[mf][2 * q + 1], af[mf], &bf[q][2]);
                }
        }

        CP_WAIT0();
        __syncthreads();
    }

    // ---- epilogue: store split-K partials ----
    {
        float* base = g_part + (size_t)ks * M_MAX * OUT_DIM;
#pragma unroll
        for (int mf = 0; mf < 4; ++mf) {
            int r0 = m0 + warp_m + mf * 16 + (lane >> 2);
#pragma unroll
            for (int nf = 0; nf < 8; ++nf) {
                int cidx = warp_n + nf * 8 + ((lane & 3) << 1);
                float2 v0 = { acc[mf][nf][0], acc[mf][nf][1] };
                float2 v1 = { acc[mf][nf][2], acc[mf][nf][3] };
                *reinterpret_cast<float2*>(base + (size_t)r0 * OUT_DIM + cidx)       = v0;
                *reinterpret_cast<float2*>(base + (size_t)(r0 + 8) * OUT_DIM + cidx) = v1;
            }
        }
    }
}

// ---------------------------------------------------------------------------
// Reduce: out = sum_{ks} part[ks] + bias
// ---------------------------------------------------------------------------
__global__ void __launch_bounds__(256) reduce_kernel(const float* __restrict__ bias,
                                                     float* __restrict__ out, int total4) {
    int i = blockIdx.x * blockDim.x + threadIdx.x;
    if (i >= total4) return;
    const int S = M_MAX * OUT_DIM / 4;
    const float4* p = reinterpret_cast<const float4*>(g_part);
    float4 a = p[i], b = p[i + S], c = p[i + 2 * S], d = p[i + 3 * S];
    float4 bb = reinterpret_cast<const float4*>(bias)[i & 63];
    float4 o;
    o.x = a.x + b.x + c.x + d.x + bb.x;
    o.y = a.y + b.y + c.y + d.y + bb.y;
    o.z = a.z + b.z + c.z + d.z + bb.z;
    o.w = a.w + b.w + c.w + d.w + bb.w;
    reinterpret_cast<float4*>(out)[i] = o;
}

extern "C" void kernel_launch(void* const* d_in, const int* in_sizes, int n_in,
                              void* d_out, int out_size) {
    const float* x      = (const float*)d_in[0];   // [M, 256]
    const float* coeffs = (const float*)d_in[1];   // [2, 256, 256, 32]
    const float* bias   = (const float*)d_in[2];   // [1, 256]
    float* out = (float*)d_out;

    int Mrows = in_sizes[0] / IN_DIM;              // 4096

    cudaFuncSetAttribute(fkan_main_kernel,
                         cudaFuncAttributeMaxDynamicSharedMemorySize, SMEM_BYTES);

    prep_coeffs_kernel<<<(1 << 19) / 256, 256>>>(coeffs);

    dim3 grid(ISPLIT, Mrows / BM);                 // (4, 32) = 128 CTAs
    fkan_main_kernel<<<grid, 256, SMEM_BYTES>>>(x);

    int total4 = Mrows * OUT_DIM / 4;
    reduce_kernel<<<(total4 + 255) / 256, 256>>>(bias, out, total4);
}

// round 5
// speedup vs baseline: 1.9572x; 1.2023x over previous
#include <cuda_runtime.h>
#include <cuda_fp16.h>
#include <cstdint>

// FourierKAN fused feature-gen + mma.sync fp16 GEMM (compute_103-safe).
// y[b,j] = sum_{i,g} cos((g+1)x_bi)C0[j,i,g] + sin((g+1)x_bi)C1[j,i,g] + bias[j]
// k layout: k = i*64 + 2*g + trig  (even k = cos, odd k = sin)
// CTA tile 128x128, 8 warps (2m x 4n), warp tile 64x32, split-K x4, 2 CTAs/SM.

#define IN_DIM   256
#define OUT_DIM  256
#define KTOT     (IN_DIM * 64)
#define BM       128
#define BN       128
#define ISPLIT   4
#define IPER     (IN_DIM / ISPLIT)   // 64
#define M_MAX    4096

#define LDRB     144                 // 72-half row stride: 16B aligned, LDSM conflict-free

#define OFF_A0   0
#define OFF_A1   18432               // 128*144
#define OFF_B0   36864
#define OFF_B1   55296
#define SMEM_BYTES 73728             // 72 KB -> 2 CTAs/SM

__device__ __half g_Wt[OUT_DIM * KTOT];              // 8.4 MB (L2-resident)
__device__ float  g_part[ISPLIT * M_MAX * OUT_DIM];  // 16 MB split-K partials

__device__ __forceinline__ unsigned sptr(const void* p) {
    return (unsigned)__cvta_generic_to_shared(p);
}

#define CP_ASYNC16(dst, src) \
    asm volatile("cp.async.cg.shared.global [%0], [%1], 16;\n" :: "r"(dst), "l"(src))
#define CP_COMMIT() asm volatile("cp.async.commit_group;\n" ::)
#define CP_WAIT0()  asm volatile("cp.async.wait_group 0;\n" ::)

__device__ __forceinline__ void mma16816(float c[4], const unsigned a[4], const unsigned* b) {
    asm volatile(
        "mma.sync.aligned.m16n8k16.row.col.f32.f16.f16.f32 "
        "{%0,%1,%2,%3}, {%4,%5,%6,%7}, {%8,%9}, {%0,%1,%2,%3};\n"
        : "+f"(c[0]), "+f"(c[1]), "+f"(c[2]), "+f"(c[3])
        : "r"(a[0]), "r"(a[1]), "r"(a[2]), "r"(a[3]), "r"(b[0]), "r"(b[1]));
}
__device__ __forceinline__ void ldsm_x4(unsigned r[4], unsigned addr) {
    asm volatile("ldmatrix.sync.aligned.m8n8.x4.shared.b16 {%0,%1,%2,%3}, [%4];\n"
                 : "=r"(r[0]), "=r"(r[1]), "=r"(r[2]), "=r"(r[3]) : "r"(addr));
}

// ---------------------------------------------------------------------------
// Prep: coeffs fp32 [2][out][in][grid] -> fp16 g_Wt[j][i*64 + 2g + trig]
// ---------------------------------------------------------------------------
__global__ void __launch_bounds__(256) prep_coeffs_kernel(const float* __restrict__ C) {
    unsigned u = blockIdx.x * blockDim.x + threadIdx.x;   // 0 .. 2^19-1
    const float4* C4 = reinterpret_cast<const float4*>(C);
    float4 c = C4[u];                 // cos coeffs, g = 4a..4a+3
    float4 s = C4[u + (1u << 19)];    // sin coeffs
    unsigned a = u & 7, i = (u >> 3) & 255, j = u >> 11;
    __half2 h0 = __floats2half2_rn(c.x, s.x);
    __half2 h1 = __floats2half2_rn(c.y, s.y);
    __half2 h2 = __floats2half2_rn(c.z, s.z);
    __half2 h3 = __floats2half2_rn(c.w, s.w);
    uint4 o;
    o.x = *reinterpret_cast<unsigned*>(&h0);
    o.y = *reinterpret_cast<unsigned*>(&h1);
    o.z = *reinterpret_cast<unsigned*>(&h2);
    o.w = *reinterpret_cast<unsigned*>(&h3);
    *reinterpret_cast<uint4*>(&g_Wt[(size_t)j * KTOT + i * 64 + a * 8]) = o;
}

// ---------------------------------------------------------------------------
// Main kernel: 256 threads, grid (ISPLIT, Mtiles, Ntiles), 2 CTAs/SM.
// ---------------------------------------------------------------------------
__global__ void __launch_bounds__(256, 2) fkan_main_kernel(const float* __restrict__ x) {
    extern __shared__ char sm[];

    const int tid  = threadIdx.x;
    const int lane = tid & 31;
    const int wid  = tid >> 5;
    const int ks   = blockIdx.x;
    const int m0   = blockIdx.y * BM;
    const int n0   = blockIdx.z * BN;
    const int i_begin = ks * IPER;

    const int warp_m = (wid & 1) * 64;
    const int warp_n = (wid >> 1) * 32;

    char* aPtr[2] = { sm + OFF_A0, sm + OFF_A1 };
    const unsigned aU32[2] = { sptr(sm + OFF_A0), sptr(sm + OFF_A1) };
    const unsigned bU32[2] = { sptr(sm + OFF_B0), sptr(sm + OFF_B1) };

    float acc[4][4][4];
#pragma unroll
    for (int a = 0; a < 4; ++a)
#pragma unroll
        for (int b = 0; b < 4; ++b)
#pragma unroll
            for (int c = 0; c < 4; ++c) acc[a][b][c] = 0.0f;

    // ---- roles ----
    const int grow = tid >> 1;          // feature row 0..127
    const int gh   = tid & 1;           // start parity (mult 1 or 2)
    const float* xsrc = x + (size_t)(m0 + grow) * IN_DIM + i_begin;

    const int bj = tid >> 1;            // B row 0..127 (2 threads/row)
    const int bh = tid & 1;             // row half (64B)
    const __half* bsrc = g_Wt + (size_t)(n0 + bj) * KTOT + i_begin * 64 + bh * 32;

    // ldmatrix byte offsets within a buffer
    const int sel = lane >> 3;
    const int rr  = lane & 7;
    unsigned aOff[4];
#pragma unroll
    for (int mf = 0; mf < 4; ++mf)
        aOff[mf] = (unsigned)((warp_m + mf * 16 + (sel & 1) * 8 + rr) * LDRB
                              + (sel >> 1) * 16);
    unsigned bOff[2];
#pragma unroll
    for (int q = 0; q < 2; ++q)
        bOff[q] = (unsigned)((warp_n + q * 16 + (sel >> 1) * 8 + rr) * LDRB
                             + (sel & 1) * 16);

    auto loadB = [&](int buf, int ii) {
        const __half* s = bsrc + ii * 64;
        unsigned d = bU32[buf] + (unsigned)(bj * LDRB + bh * 64);
#pragma unroll
        for (int seg = 0; seg < 4; ++seg)
            CP_ASYNC16(d + seg * 16, s + seg * 8);
    };

    auto genA = [&](int buf, int ii) {
        float xv = __ldg(xsrc + ii);
        float s1, c1;
        sincosf(xv, &s1, &c1);
        float c2 = __fmaf_rn(2.f * c1, c1, -1.f);   // cos 2x
        float s2 = 2.f * s1 * c1;                   // sin 2x
        float ck = gh ? c2 : c1;                    // start mult = gh+1
        float sk = gh ? s2 : s1;
        __half* arow = reinterpret_cast<__half*>(aPtr[buf] + grow * LDRB) + 2 * gh;
#pragma unroll
        for (int n = 0; n < 16; ++n) {              // mult = gh+1 + 2n
            __half2 v = __floats2half2_rn(ck, sk);
            *reinterpret_cast<__half2*>(arow + 4 * n) = v;
            float nc = ck * c2 - sk * s2;
            float ns = sk * c2 + ck * s2;
            ck = nc; sk = ns;
        }
    };

    // ---- prologue ----
    loadB(0, 0);
    CP_COMMIT();
    genA(0, 0);
    CP_WAIT0();
    __syncthreads();

    // ---- main loop ----
    for (int ii = 0; ii < IPER; ++ii) {
        const int cur = ii & 1;
        const int nxt = cur ^ 1;

        if (ii + 1 < IPER) {
            loadB(nxt, ii + 1);
            CP_COMMIT();
            genA(nxt, ii + 1);
        }

#pragma unroll
        for (int kk = 0; kk < 4; ++kk) {
            const unsigned kB = (unsigned)(kk * 32);
            unsigned af[4][4], bf[2][4];
#pragma unroll
            for (int mf = 0; mf < 4; ++mf) ldsm_x4(af[mf], aU32[cur] + aOff[mf] + kB);
#pragma unroll
            for (int q = 0; q < 2; ++q)    ldsm_x4(bf[q],  bU32[cur] + bOff[q] + kB);
#pragma unroll
            for (int mf = 0; mf < 4; ++mf)
#pragma unroll
                for (int q = 0; q < 2; ++q) {
                    mma16816(acc[mf][2 * q],     af[mf], &bf[q][0]);
                    mma16816(acc[mf][2 * q + 1], af[mf], &bf[q][2]);
                }
        }

        CP_WAIT0();
        __syncthreads();
    }

    // ---- epilogue: store split-K partials ----
    {
        float* base = g_part + (size_t)ks * M_MAX * OUT_DIM;
#pragma unroll
        for (int mf = 0; mf < 4; ++mf) {
            int r0 = m0 + warp_m + mf * 16 + (lane >> 2);
#pragma unroll
            for (int nf = 0; nf < 4; ++nf) {
                int cidx = n0 + warp_n + nf * 8 + ((lane & 3) << 1);
                float2 v0 = { acc[mf][nf][0], acc[mf][nf][1] };
                float2 v1 = { acc[mf][nf][2], acc[mf][nf][3] };
                *reinterpret_cast<float2*>(base + (size_t)r0 * OUT_DIM + cidx)       = v0;
                *reinterpret_cast<float2*>(base + (size_t)(r0 + 8) * OUT_DIM + cidx) = v1;
            }
        }
    }
}

// ---------------------------------------------------------------------------
// Reduce: out = sum_{ks} part[ks] + bias
// ---------------------------------------------------------------------------
__global__ void __launch_bounds__(256) reduce_kernel(const float* __restrict__ bias,
                                                     float* __restrict__ out, int total4) {
    int i = blockIdx.x * blockDim.x + threadIdx.x;
    if (i >= total4) return;
    const int S = M_MAX * OUT_DIM / 4;
    const float4* p = reinterpret_cast<const float4*>(g_part);
    float4 a = p[i], b = p[i + S], c = p[i + 2 * S], d = p[i + 3 * S];
    float4 bb = reinterpret_cast<const float4*>(bias)[i & 63];
    float4 o;
    o.x = a.x + b.x + c.x + d.x + bb.x;
    o.y = a.y + b.y + c.y + d.y + bb.y;
    o.z = a.z + b.z + c.z + d.z + bb.z;
    o.w = a.w + b.w + c.w + d.w + bb.w;
    reinterpret_cast<float4*>(out)[i] = o;
}

extern "C" void kernel_launch(void* const* d_in, const int* in_sizes, int n_in,
                              void* d_out, int out_size) {
    const float* x      = (const float*)d_in[0];   // [M, 256]
    const float* coeffs = (const float*)d_in[1];   // [2, 256, 256, 32]
    const float* bias   = (const float*)d_in[2];   // [1, 256]
    float* out = (float*)d_out;

    int Mrows = in_sizes[0] / IN_DIM;              // 4096

    cudaFuncSetAttribute(fkan_main_kernel,
                         cudaFuncAttributeMaxDynamicSharedMemorySize, SMEM_BYTES);

    prep_coeffs_kernel<<<(1 << 19) / 256, 256>>>(coeffs);

    dim3 grid(ISPLIT, Mrows / BM, OUT_DIM / BN);   // (4, 32, 2) = 256 CTAs
    fkan_main_kernel<<<grid, 256, SMEM_BYTES>>>(x);

    int total4 = Mrows * OUT_DIM / 4;
    reduce_kernel<<<(total4 + 255) / 256, 256>>>(bias, out, total4);
}